// round 17
// baseline (speedup 1.0000x reference)
#include <cuda_runtime.h>
#include <cuda_bf16.h>

// position_encoder: out[b,s,j] = x[b,s,j] + (j even ? sin : cos)(s / 10000^((j+1)/1024))
// B=4, S=8192, D=1024, fp32.
// Persistent single-wave variant of the proven R8 shell: grid = 444 blocks
// (148 SMs x 3 resident), grid-stride loop over the 4096 two-row chunks.
// Per chunk: direct sincosf seeding from fp64 theta (compile-time fd table),
// 4 batch-strided float4 loads front-batched, 4 adds, 4 stores. Iterations
// are independent -> loads of chunk i+1 overlap stores of chunk i; no wave
// transitions.

#define PE_S      8192
#define PE_D      1024
#define PE_B      4
#define PE_ROWS   2                 // rows per chunk
#define PE_D4     (PE_D / 4)        // 256 float4 per row
#define N_CHUNKS  (PE_S / PE_ROWS)  // 4096
#define GRID_PERS 444               // 148 SMs x 3 blocks

struct PETab { double fd[PE_D]; };

constexpr double cexp_small(double t) {
    double r = 1.0;
    for (int k = 24; k >= 1; --k) r = 1.0 + t * r / (double)k;
    return r;
}
constexpr PETab make_tab() {
    PETab t{};
    const double kexp = 13.287712379549449 / 1024.0;  // log2(10000)/1024
    const double ln2  = 0.6931471805599453;
    for (int j = 0; j < PE_D; ++j) {
        const double e = (double)(j + 1) * kexp;
        const int    n = (int)e;
        const double f = e - (double)n;
        double v = cexp_small(-f * ln2);              // 2^-frac
        for (int i = 0; i < n; ++i) v *= 0.5;         // * 2^-int (exact)
        t.fd[j] = v;
    }
    return t;
}
__device__ constexpr PETab g_tab = make_tab();

__global__ __launch_bounds__(512, 3)
void position_encoder_kernel(const float4* __restrict__ x, float4* __restrict__ out) {
    const unsigned d4 = threadIdx.x & (PE_D4 - 1);    // 0..255 -> column group
    const unsigned r  = threadIdx.x >> 8;             // 0..1   -> row within chunk
    const unsigned j0 = d4 * 4;
    const unsigned bstride = (unsigned)PE_S * PE_D4;  // float4 per batch

    // per-thread fd constants (loop-invariant)
    const double fd0 = g_tab.fd[j0 + 0];
    const double fd1 = g_tab.fd[j0 + 1];
    const double fd2 = g_tab.fd[j0 + 2];
    const double fd3 = g_tab.fd[j0 + 3];

    for (unsigned chunk = blockIdx.x; chunk < N_CHUNKS; chunk += GRID_PERS) {
        const unsigned s = chunk * PE_ROWS + r;       // global row

        // pos vector for (s, j0..j0+3): fp64 theta -> accurate fp32 sincos
        const double sd = (double)s;
        float sn0, cs0, sn1, cs1, sn2, cs2, sn3, cs3;
        sincosf((float)(sd * fd0), &sn0, &cs0);
        sincosf((float)(sd * fd1), &sn1, &cs1);
        sincosf((float)(sd * fd2), &sn2, &cs2);
        sincosf((float)(sd * fd3), &sn3, &cs3);
        const float4 p = make_float4(sn0, cs1, sn2, cs3);

        const unsigned base = s * PE_D4 + d4;
        const float4* __restrict__ xp = x   + base;
        float4* __restrict__       op = out + base;

        // front-batch the 4 batch loads, then add, then store
        float4 v[PE_B];
#pragma unroll
        for (int b = 0; b < PE_B; b++) v[b] = xp[(size_t)b * bstride];
#pragma unroll
        for (int b = 0; b < PE_B; b++) {
            v[b].x += p.x; v[b].y += p.y; v[b].z += p.z; v[b].w += p.w;
        }
#pragma unroll
        for (int b = 0; b < PE_B; b++) op[(size_t)b * bstride] = v[b];
    }
}

extern "C" void kernel_launch(void* const* d_in, const int* in_sizes, int n_in,
                              void* d_out, int out_size) {
    (void)in_sizes; (void)n_in; (void)out_size;
    const float4* x = (const float4*)d_in[0];
    float4* out = (float4*)d_out;
    position_encoder_kernel<<<GRID_PERS, 512>>>(x, out);
}